// round 16
// baseline (speedup 1.0000x reference)
#include <cuda_runtime.h>

#define SEQ   512
#define BATCH 256
#define INDIM 15
#define HID   512
#define NB    128
#define TPB   256

typedef unsigned long long u64;

// ---- persistent device state (no allocations) ----
__device__ float g_xT[SEQ * INDIM * BATCH];   // [t][c][b]
__device__ float g_h1[2][HID * BATCH];        // [unit][batch], ping-pong
__device__ float g_h2[2][HID * BATCH];
__device__ float g_fc1[64 * BATCH];
__device__ unsigned g_arrive;
__device__ unsigned g_release;

__global__ void sync_init_kernel() { g_arrive = 0u; g_release = 0u; }

// ---- f32x2 helpers ----
__device__ __forceinline__ u64 pk2(float a, float b) {
    u64 r; asm("mov.b64 %0, {%1,%2};" : "=l"(r) : "f"(a), "f"(b)); return r;
}
__device__ __forceinline__ void upk2(u64 v, float& a, float& b) {
    asm("mov.b64 {%0,%1}, %2;" : "=f"(a), "=f"(b) : "l"(v));
}
__device__ __forceinline__ u64 ffma2(u64 a, u64 b, u64 c) {
    u64 d; asm("fma.rn.f32x2 %0, %1, %2, %3;" : "=l"(d) : "l"(a), "l"(b), "l"(c)); return d;
}

// ---- cp.async staging (L2-only path; also avoids stale L1) ----
__device__ __forceinline__ void cp16(unsigned saddr, const void* g) {
    asm volatile("cp.async.cg.shared.global [%0], [%1], 16;" :: "r"(saddr), "l"(g));
}
__device__ __forceinline__ void cp_commit() { asm volatile("cp.async.commit_group;" ::: "memory"); }
__device__ __forceinline__ void cp_wait0()  { asm volatile("cp.async.wait_group 0;"  ::: "memory"); }

__device__ __forceinline__ void stage(float* dst, const float* src, int nf4, int tid) {
    unsigned s = (unsigned)__cvta_generic_to_shared(dst);
    const float4* g = (const float4*)src;
#pragma unroll 4
    for (int q = tid; q < nf4; q += TPB) cp16(s + q * 16, (const void*)(g + q));
}

// ---- grid-wide barrier (counters reset by init kernel each launch) ----
__device__ __forceinline__ void grid_sync(unsigned k) {
    __syncthreads();
    if (threadIdx.x == 0) {
        __threadfence();
        if (atomicAdd(&g_arrive, 1u) == k * (unsigned)NB - 1u) {
            asm volatile("st.release.gpu.global.u32 [%0], %1;" :: "l"(&g_release), "r"(k) : "memory");
        } else {
            unsigned v;
            do { asm volatile("ld.acquire.gpu.global.u32 %0, [%1];" : "=r"(v) : "l"(&g_release) : "memory"); }
            while (v < k);
        }
    }
    __syncthreads();
}

// ---- GEMM microkernel: thread = unit cx (4 gates) x 4 batches (by) ----
// Wt row k: 16 floats = [i0 f0 g0 o0 i1 ...]; Hs row k: 256 floats (batch)
template<int NK>
__device__ __forceinline__ void gemm_tile(u64 acc[4][2], const float* __restrict__ Wt,
                                          const float* __restrict__ Hs, int cx, int by) {
#pragma unroll
    for (int k = 0; k < NK; ++k) {
        ulonglong2 wp = *(const ulonglong2*)(Wt + k * 16 + cx * 4);   // {i,f},{g,o}
        float4 hq = *(const float4*)(Hs + k * BATCH + by * 4);
        u64 h0 = pk2(hq.x, hq.x), h1v = pk2(hq.y, hq.y);
        u64 h2v = pk2(hq.z, hq.z), h3v = pk2(hq.w, hq.w);
        acc[0][0] = ffma2(h0,  wp.x, acc[0][0]); acc[0][1] = ffma2(h0,  wp.y, acc[0][1]);
        acc[1][0] = ffma2(h1v, wp.x, acc[1][0]); acc[1][1] = ffma2(h1v, wp.y, acc[1][1]);
        acc[2][0] = ffma2(h2v, wp.x, acc[2][0]); acc[2][1] = ffma2(h2v, wp.y, acc[2][1]);
        acc[3][0] = ffma2(h3v, wp.x, acc[3][0]); acc[3][1] = ffma2(h3v, wp.y, acc[3][1]);
    }
}

__device__ __forceinline__ float sigf(float x) { return 1.0f / (1.0f + __expf(-x)); }

// SMEM floats: Hs(2x8192)=16384 | Wt1 8192 | Wt2a 8192 | Wt2b 8192 | Wtx 256 | bc1 16 | bc2 16
#define SMEM_FLOATS 41248
#define SMEM_BYTES  (SMEM_FLOATS * 4)

__global__ void __launch_bounds__(TPB, 1)
lstm2_persist(const float* __restrict__ x,
              const float* __restrict__ Wih1, const float* __restrict__ Whh1,
              const float* __restrict__ bih1, const float* __restrict__ bhh1,
              const float* __restrict__ Wih2, const float* __restrict__ Whh2,
              const float* __restrict__ bih2, const float* __restrict__ bhh2,
              const float* __restrict__ fc1w, const float* __restrict__ fc1b,
              const float* __restrict__ fcw,  const float* __restrict__ fcb,
              float* __restrict__ out)
{
    extern __shared__ float sm[];
    float* Hsm  = sm;
    float* Wt1  = sm + 16384;
    float* Wt2a = Wt1 + 8192;
    float* Wt2b = Wt2a + 8192;
    float* Wtx  = Wt2b + 8192;
    float* bc1  = Wtx + 256;
    float* bc2  = bc1 + 16;

    const int tid = threadIdx.x;
    const int blk = blockIdx.x;
    const int cx  = tid & 3;
    const int by  = tid >> 2;
    const int u   = blk * 4 + cx;

    // ---- prologue: transposed weight slices (col c = 4*unit+gate; row r = gate*512+unit_global)
    for (int idx = tid; idx < 16 * 512; idx += TPB) {
        int c = idx >> 9, k = idx & 511;
        int r = (c & 3) * 512 + blk * 4 + (c >> 2);
        Wt1[k * 16 + c]  = Whh1[r * 512 + k];
        Wt2a[k * 16 + c] = Wih2[r * 512 + k];
        Wt2b[k * 16 + c] = Whh2[r * 512 + k];
    }
    if (tid < 16 * INDIM) {
        int c = tid / INDIM, k = tid % INDIM;
        int r = (c & 3) * 512 + blk * 4 + (c >> 2);
        Wtx[k * 16 + c] = Wih1[r * INDIM + k];
    }
    if (tid < 16) {
        int r = (tid & 3) * 512 + blk * 4 + (tid >> 2);
        bc1[tid] = bih1[r] + bhh1[r];
        bc2[tid] = bih2[r] + bhh2[r];
    }
    // zero h(-1) (parity 1); each thread owns a unique 16B slice
    {
        float4 z = make_float4(0.f, 0.f, 0.f, 0.f);
        *(float4*)&g_h1[1][u * BATCH + by * 4] = z;
        *(float4*)&g_h2[1][u * BATCH + by * 4] = z;
    }
    // transpose x: g_xT[(t*15+c)*256+b] = x[(t*256+b)*15+c]
    for (int idx = blk * TPB + tid; idx < SEQ * INDIM * BATCH; idx += NB * TPB) {
        int b = idx & (BATCH - 1);
        int rest = idx >> 8;
        int c = rest % INDIM, t = rest / INDIM;
        g_xT[idx] = x[(t * BATCH + b) * INDIM + c];
    }

    float c1s[4] = {0.f, 0.f, 0.f, 0.f};
    float c2s[4] = {0.f, 0.f, 0.f, 0.f};
    unsigned barno = 1;
    grid_sync(barno);

    const float4 bq1 = ((const float4*)bc1)[cx];
    const float4 bq2 = ((const float4*)bc2)[cx];
    const u64 b1lo = pk2(bq1.x, bq1.y), b1hi = pk2(bq1.z, bq1.w);
    const u64 b2lo = pk2(bq2.x, bq2.y), b2hi = pk2(bq2.z, bq2.w);

    for (int t = 0; t < SEQ; ++t) {
        const int p = t & 1;

        // ---- layer 1 ----
        {
            const float* h1r = g_h1[p ^ 1];
            u64 acc[4][2] = {{b1lo,b1hi},{b1lo,b1hi},{b1lo,b1hi},{b1lo,b1hi}};
            stage(Hsm, h1r, 2048, tid); cp_commit();
            for (int tile = 0; tile < 17; ++tile) {
                float* buf = Hsm + (tile & 1) * 8192;
                cp_wait0();
                __syncthreads();
                if (tile < 16) {
                    float* nbuf = Hsm + ((tile + 1) & 1) * 8192;
                    if (tile < 15) stage(nbuf, h1r + (tile + 1) * 8192, 2048, tid);
                    else           stage(nbuf, &g_xT[t * INDIM * BATCH], INDIM * BATCH / 4, tid);
                    cp_commit();
                    gemm_tile<32>(acc, Wt1 + tile * 512, buf, cx, by);
                } else {
                    gemm_tile<INDIM>(acc, Wtx, buf, cx, by);
                }
            }
            float hb[4];
#pragma unroll
            for (int b = 0; b < 4; ++b) {
                float gi, gf, gg, go;
                upk2(acc[b][0], gi, gf);
                upk2(acc[b][1], gg, go);
                float cc = sigf(gf) * c1s[b] + sigf(gi) * tanhf(gg);
                c1s[b] = cc;
                hb[b] = sigf(go) * tanhf(cc);
            }
            *(float4*)&g_h1[p][u * BATCH + by * 4] = make_float4(hb[0], hb[1], hb[2], hb[3]);
        }
        grid_sync(++barno);

        // ---- layer 2 ----
        {
            const float* h1c = g_h1[p];
            const float* h2r = g_h2[p ^ 1];
            u64 acc[4][2] = {{b2lo,b2hi},{b2lo,b2hi},{b2lo,b2hi},{b2lo,b2hi}};
            stage(Hsm, h1c, 2048, tid); cp_commit();
            for (int tile = 0; tile < 32; ++tile) {
                float* buf = Hsm + (tile & 1) * 8192;
                cp_wait0();
                __syncthreads();
                if (tile + 1 < 32) {
                    float* nbuf = Hsm + ((tile + 1) & 1) * 8192;
                    const float* src = (tile + 1 < 16) ? h1c + (tile + 1) * 8192
                                                       : h2r + (tile + 1 - 16) * 8192;
                    stage(nbuf, src, 2048, tid);
                    cp_commit();
                }
                const float* W = (tile < 16) ? Wt2a + tile * 512 : Wt2b + (tile - 16) * 512;
                gemm_tile<32>(acc, W, buf, cx, by);
            }
            float hb[4];
#pragma unroll
            for (int b = 0; b < 4; ++b) {
                float gi, gf, gg, go;
                upk2(acc[b][0], gi, gf);
                upk2(acc[b][1], gg, go);
                float cc = sigf(gf) * c2s[b] + sigf(gi) * tanhf(gg);
                c2s[b] = cc;
                hb[b] = sigf(go) * tanhf(cc);
            }
            *(float4*)&g_h2[p][u * BATCH + by * 4] = make_float4(hb[0], hb[1], hb[2], hb[3]);
        }
        grid_sync(++barno);
    }

    // ---- MLP head: h2 final is parity (SEQ-1)&1 = 1 ----
    const float* h2f = g_h2[1];
    if (blk < 64) {   // block j computes fc1 column j for all batches
        float s = fc1b[blk];
        for (int k = 0; k < HID; ++k)
            s += fmaxf(__ldcg(&h2f[k * BATCH + tid]), 0.f) * fc1w[blk * HID + k];
        g_fc1[blk * BATCH + tid] = fmaxf(s, 0.f);
    }
    grid_sync(++barno);
    if (blk == 0) {
        float s = fcb[0];
#pragma unroll
        for (int j = 0; j < 64; ++j)
            s += __ldcg(&g_fc1[j * BATCH + tid]) * fcw[j];
        out[tid] = 2.0f * s;   // reference returns out + out
    }
}

extern "C" void kernel_launch(void* const* d_in, const int* in_sizes, int n_in,
                              void* d_out, int out_size) {
    (void)in_sizes; (void)n_in; (void)out_size;
    cudaFuncSetAttribute(lstm2_persist, cudaFuncAttributeMaxDynamicSharedMemorySize, SMEM_BYTES);
    sync_init_kernel<<<1, 1>>>();
    lstm2_persist<<<NB, TPB, SMEM_BYTES>>>(
        (const float*)d_in[0],
        (const float*)d_in[1], (const float*)d_in[2],
        (const float*)d_in[3], (const float*)d_in[4],
        (const float*)d_in[5], (const float*)d_in[6],
        (const float*)d_in[7], (const float*)d_in[8],
        (const float*)d_in[9], (const float*)d_in[10],
        (const float*)d_in[11], (const float*)d_in[12],
        (float*)d_out);
}